// round 6
// baseline (speedup 1.0000x reference)
#include <cuda_runtime.h>
#include <cstdint>

// ---------------------------------------------------------------------------
// Problem constants
// ---------------------------------------------------------------------------
#define BB    32
#define TT    1024
#define CC    512
#define DD    256
#define UU    256
#define OO    256
#define MTOT  (BB*TT)          // 32768

__device__ float g_xin[(size_t)MTOT * DD];
__device__ float g_xz [(size_t)MTOT * 4 * UU];
__device__ float g_hs [(size_t)MTOT * UU];

// noops: shift ncu capture (empirically lands on absolute launch idx 4) onto LSTM
__global__ void noop_kernel(int* p) { if (p) *p = 0; }

// ---------------------------------------------------------------------------
// Tiled fp32 GEMM (unchanged): C[M,N] = A[M,K] @ W[K,N] + bias[N]
// ---------------------------------------------------------------------------
__global__ __launch_bounds__(256) void gemm_bias_kernel(
    const float* __restrict__ A, const float* __restrict__ W,
    const float* __restrict__ bias, float* __restrict__ C,
    int M, int N, int K)
{
    __shared__ float As[16][128];
    __shared__ float Bs[16][64];

    const int tid = threadIdx.x;
    const int tx  = tid & 15;
    const int ty  = tid >> 4;
    const int m0  = blockIdx.y * 128;
    const int n0  = blockIdx.x * 64;

    const int arow = tid >> 2;
    const int akc  = (tid & 3) * 4;
    const int brow = tid >> 4;
    const int bnc  = (tid & 15) * 4;

    float acc[8][4];
    #pragma unroll
    for (int i = 0; i < 8; i++)
        #pragma unroll
        for (int j = 0; j < 4; j++) acc[i][j] = 0.f;

    for (int kt = 0; kt < K; kt += 16) {
        #pragma unroll
        for (int h = 0; h < 2; h++) {
            int r = arow + h * 64;
            float4 a = *(const float4*)&A[(size_t)(m0 + r) * K + kt + akc];
            As[akc + 0][r] = a.x;
            As[akc + 1][r] = a.y;
            As[akc + 2][r] = a.z;
            As[akc + 3][r] = a.w;
        }
        {
            float4 b = *(const float4*)&W[(size_t)(kt + brow) * N + n0 + bnc];
            *(float4*)&Bs[brow][bnc] = b;
        }
        __syncthreads();

        #pragma unroll
        for (int kk = 0; kk < 16; kk++) {
            float4 b4 = *(const float4*)&Bs[kk][tx * 4];
            float4 a0 = *(const float4*)&As[kk][ty * 8];
            float4 a1 = *(const float4*)&As[kk][ty * 8 + 4];
            float a[8] = {a0.x, a0.y, a0.z, a0.w, a1.x, a1.y, a1.z, a1.w};
            #pragma unroll
            for (int i = 0; i < 8; i++) {
                acc[i][0] += a[i] * b4.x;
                acc[i][1] += a[i] * b4.y;
                acc[i][2] += a[i] * b4.z;
                acc[i][3] += a[i] * b4.w;
            }
        }
        __syncthreads();
    }

    float4 bv = *(const float4*)&bias[n0 + tx * 4];
    #pragma unroll
    for (int i = 0; i < 8; i++) {
        float4 o;
        o.x = acc[i][0] + bv.x;
        o.y = acc[i][1] + bv.y;
        o.z = acc[i][2] + bv.z;
        o.w = acc[i][3] + bv.w;
        *(float4*)&C[(size_t)(m0 + ty * 8 + i) * N + n0 + tx * 4] = o;
    }
}

// ---------------------------------------------------------------------------
// LSTM scan v5: 512 threads / 16 warps.
//   warp w: k-chunk kc=w&7 (32 k), col-half ch=w>>3 (64 of 128 cols).
//   thread: 2 cols (c0=ch*64+2l), 32 k -> Rreg = 32 u64 (64 regs, NO spill).
//   Exchange: stage 256B -> one cp.async.bulk per peer, per-source mbarriers,
//   warps 2..15 run ahead (bar.arrive), gate warps 0,1 reduce+gates+push.
// ---------------------------------------------------------------------------
#define CLS 8
#define LSTM_THREADS 512

__device__ __forceinline__ float sigm_f(float x) {
    return 1.f / (1.f + __expf(-x));
}
__device__ __forceinline__ float tanh_f(float x) {
    return 2.f / (1.f + __expf(-2.f * x)) - 1.f;
}

#define FMA2(acc, a, b) \
    asm("fma.rn.f32x2 %0, %1, %2, %0;" : "+l"(acc) : "l"(a), "l"(b))

#define MBAR_INIT(addr, cnt) \
    asm volatile("mbarrier.init.shared.b64 [%0], %1;" :: "r"(addr), "r"(cnt) : "memory")

#define MBAR_EXPECT_TX(addr, tx) \
    asm volatile("mbarrier.arrive.expect_tx.shared.b64 _, [%0], %1;" :: "r"(addr), "r"(tx) : "memory")

#define MBAR_WAIT(addr, par) do {                                                  \
    asm volatile("{\n\t.reg .pred P;\n"                                            \
                 "W_%=:\n\t"                                                       \
                 "mbarrier.try_wait.parity.acquire.cluster.shared::cta.b64 "       \
                 "P, [%0], %1, 0x80;\n\t"                                          \
                 "@!P bra W_%=;\n\t}"                                              \
                 :: "r"(addr), "r"(par) : "memory");                               \
} while (0)

__global__ void __cluster_dims__(CLS, 1, 1) __launch_bounds__(LSTM_THREADS, 1)
lstm_kernel(const float* __restrict__ xz, const float* __restrict__ R,
            float* __restrict__ hs)
{
    __shared__ __align__(16) float h2[2 * 512];          // [buf][k=256][b=2]
    __shared__ __align__(16) float parts[2 * 8 * 2 * 128]; // [buf][kc][b][c]
    __shared__ __align__(16) float hstage[64];           // [u=32][b=2]
    __shared__ __align__(8)  unsigned long long mbar[16]; // [buf][src=8]

    const int tid  = threadIdx.x;
    const int rank = blockIdx.x;
    const int b0   = blockIdx.y * 2;
    const int w    = tid >> 5;
    const int l    = tid & 31;
    const int kc   = w & 7;              // k-chunk
    const int ch   = w >> 3;             // column half

    // ---- R sub-tile -> registers: k = kc*32..+32, cols (c0, c0+1)
    const int c0   = ch * 64 + 2 * l;          // local col, even
    const int gcol = (c0 >> 5) * 256 + rank * 32 + (c0 & 31);
    unsigned long long Rreg[32];
    #pragma unroll
    for (int j = 0; j < 32; j++)
        Rreg[j] = *(const unsigned long long*)&R[(size_t)(kc * 32 + j) * 1024 + gcol];

    for (int i = tid; i < 1024; i += LSTM_THREADS) h2[i] = 0.f;

    const unsigned mb0 = (unsigned)__cvta_generic_to_shared(&mbar[0]);
    if (tid == 0) {
        #pragma unroll
        for (int i = 0; i < 16; i++) {
            MBAR_INIT(mb0 + i * 8, 1);
            MBAR_EXPECT_TX(mb0 + i * 8, 256);
        }
        asm volatile("fence.mbarrier_init.release.cluster;" ::: "memory");
    }
    __syncthreads();
    asm volatile("barrier.cluster.arrive.aligned;" ::: "memory");
    asm volatile("barrier.cluster.wait.aligned;"   ::: "memory");

    const int gb = tid >> 5;             // gate-thread batch (tid<64)
    const int gu = tid & 31;             // gate-thread unit
    float creg = 0.f;
    int ph0 = 0, ph1 = 0;

    // precomputed remote addresses for the bulk push (threads 0..7 only use own)
    unsigned rdl = 0, rml = 0;
    if (tid < 8) {
        const unsigned dl0 = (unsigned)__cvta_generic_to_shared(&h2[rank * 64]);
        const unsigned ml0 = mb0 + (unsigned)(rank * 8);
        asm volatile("mapa.shared::cluster.u32 %0, %1, %2;"
                     : "=r"(rdl) : "r"(dl0), "r"(tid));
        asm volatile("mapa.shared::cluster.u32 %0, %1, %2;"
                     : "=r"(rml) : "r"(ml0), "r"(tid));
    }
    const unsigned src_l = (unsigned)__cvta_generic_to_shared(&hstage[0]);
    const unsigned mwait0 = mb0 + (unsigned)(kc * 8);   // buf0, src=kc

    for (int t = 0; t < TT; t++) {
        const int pb = t & 1;

        // xz prefetch (gate threads), before any wait
        float xzv0 = 0.f, xzv1 = 0.f, xzv2 = 0.f, xzv3 = 0.f;
        if (tid < 64) {
            size_t base = ((size_t)(b0 + gb) * TT + t) * 1024 + rank * 32 + gu;
            xzv0 = xz[base];
            xzv1 = xz[base + 256];
            xzv2 = xz[base + 512];
            xzv3 = xz[base + 768];
        }

        // wait only for slice kc (from rank kc)
        if (t > 0) {
            const unsigned m = mwait0 + (unsigned)(pb * 64);
            if (pb) { MBAR_WAIT(m, ph1); ph1 ^= 1; }
            else    { MBAR_WAIT(m, ph0); ph0 ^= 1; }
            if (l == 0 && w < 8) MBAR_EXPECT_TX(m, 256);  // re-arm for t+2
        }

        // ---- MMA: cols (c0,c0+1), k in [kc*32, kc*32+32), batches 0,1
        unsigned long long a0 = 0ull, a1 = 0ull;
        const float2* hb = (const float2*)(h2 + pb * 512) + kc * 32;
        #pragma unroll
        for (int j = 0; j < 32; j++) {
            float2 hh = hb[j];
            unsigned hx = __float_as_uint(hh.x);
            unsigned hy = __float_as_uint(hh.y);
            unsigned long long hp0, hp1;
            asm("mov.b64 %0, {%1, %1};" : "=l"(hp0) : "r"(hx));
            asm("mov.b64 %0, {%1, %1};" : "=l"(hp1) : "r"(hy));
            FMA2(a0, Rreg[j], hp0);
            FMA2(a1, Rreg[j], hp1);
        }
        {
            float* pbuf = parts + pb * 2048;
            unsigned p0, p1;
            asm("mov.b64 {%0, %1}, %2;" : "=r"(p0), "=r"(p1) : "l"(a0));
            *(float2*)&pbuf[(kc * 2 + 0) * 128 + c0] =
                make_float2(__uint_as_float(p0), __uint_as_float(p1));
            asm("mov.b64 {%0, %1}, %2;" : "=r"(p0), "=r"(p1) : "l"(a1));
            *(float2*)&pbuf[(kc * 2 + 1) * 128 + c0] =
                make_float2(__uint_as_float(p0), __uint_as_float(p1));
        }

        if (w >= 2) {
            asm volatile("bar.arrive 2, %0;" :: "n"(LSTM_THREADS) : "memory");
            continue;                        // run ahead into next step
        }
        asm volatile("bar.sync 2, %0;" :: "n"(LSTM_THREADS) : "memory");

        // ---- gate phase (warps 0,1 = 64 gate threads) ----
        {
            const float* pbuf = parts + pb * 2048;
            float z0 = xzv0, z1 = xzv1, z2 = xzv2, z3 = xzv3;
            #pragma unroll
            for (int kk = 0; kk < 8; kk++) {
                const float* p = &pbuf[(kk * 2 + gb) * 128];
                z0 += p[gu];
                z1 += p[32 + gu];
                z2 += p[64 + gu];
                z3 += p[96 + gu];
            }
            float ig = sigm_f(z0);
            float fg = sigm_f(z1);
            float gg = tanh_f(z2);
            float og = sigm_f(z3);
            creg = fg * creg + ig * gg;
            float h = og * tanh_f(creg);

            if (t < TT - 1) {
                hstage[gu * 2 + gb] = h;
                asm volatile("bar.sync 1, 64;" ::: "memory");
                if (tid < 8) {
                    asm volatile("fence.proxy.async.shared::cta;" ::: "memory");
                    const int nb = pb ^ 1;
                    const unsigned rd = rdl + (unsigned)(nb * 2048);
                    const unsigned rm = rml + (unsigned)(nb * 64);
                    asm volatile(
                        "cp.async.bulk.shared::cluster.shared::cta"
                        ".mbarrier::complete_tx::bytes [%0], [%1], 256, [%2];"
                        :: "r"(rd), "r"(src_l), "r"(rm) : "memory");
                }
            }
            hs[((size_t)(b0 + gb) * TT + t) * UU + rank * 32 + gu] = h;
        }
    }

    asm volatile("barrier.cluster.arrive.aligned;" ::: "memory");
    asm volatile("barrier.cluster.wait.aligned;"   ::: "memory");
}

// ---------------------------------------------------------------------------
// launch
// ---------------------------------------------------------------------------
extern "C" void kernel_launch(void* const* d_in, const int* in_sizes, int n_in,
                              void* d_out, int out_size)
{
    const float* x      = (const float*)d_in[0];
    const float* w_in   = (const float*)d_in[1];
    const float* b_in   = (const float*)d_in[2];
    const float* kernel = (const float*)d_in[3];
    const float* rec_k  = (const float*)d_in[4];
    const float* bias   = (const float*)d_in[5];
    const float* w_out  = (const float*)d_in[6];
    const float* b_out  = (const float*)d_in[7];
    float* out = (float*)d_out;

    float *p_xin, *p_xz, *p_hs;
    cudaGetSymbolAddress((void**)&p_xin, g_xin);
    cudaGetSymbolAddress((void**)&p_xz,  g_xz);
    cudaGetSymbolAddress((void**)&p_hs,  g_hs);

    // 2 noops: empirically ncu captures absolute launch idx 4 -> the LSTM
    noop_kernel<<<1, 32>>>(nullptr);
    noop_kernel<<<1, 32>>>(nullptr);

    // 1) xin = x @ w_in + b_in          [32768,512]x[512,256]
    gemm_bias_kernel<<<dim3(DD / 64, MTOT / 128), 256>>>(
        x, w_in, b_in, p_xin, MTOT, DD, CC);

    // 2) xz = xin @ kernel + bias       [32768,256]x[256,1024]
    gemm_bias_kernel<<<dim3((4 * UU) / 64, MTOT / 128), 256>>>(
        p_xin, kernel, bias, p_xz, MTOT, 4 * UU, DD);

    // 3) LSTM scan over T=1024
    lstm_kernel<<<dim3(CLS, BB / 2), LSTM_THREADS>>>(p_xz, rec_k, p_hs);

    // 4) out = hs @ w_out + b_out       [32768,256]x[256,256]
    gemm_bias_kernel<<<dim3(OO / 64, MTOT / 128), 256>>>(
        p_hs, w_out, b_out, out, MTOT, OO, UU);
}